// round 14
// baseline (speedup 1.0000x reference)
#include <cuda_runtime.h>
#include <cstdint>

// Flow1 via mma.sync m16n8k16 bf16 (3-product compensation), packed pre-split
// weights, m32 x n16 warp tiles at 2 CTAs/SM, group-counted cp.async staging.
// R14: hi/lo pairs interleaved at adjacent words -> all split-weight and H
// traffic uses LDS.64/STS.64 (half the instructions, same bytes, pitch 72
// keeps 64-bit phases conflict-free).
// B=262144 rows, Z=128, ZH=64, HS=50 (padded 56), 4 couplings.
// Out: [ z (B*128) | logpz (B) | logqz (B) ] fp32.

#define ZZ 128
#define ZH 64
#define HS 50
#define NC 4
#define TPB 256
#define MR 64
#define PZ 72      // fp32 z pitch (floats); 72 % 32 = 8 -> conflict-free LDS.64
#define KPI 36     // k-pairs per row
#define KP2 72     // interleaved word pitch: 36 kp x {h,l}

// global packed-weight layout (per coupling), words
#define GW12 4032              // W1/W2 block starts after W0 (56 x 72)
#define W1r  0                 // 64 x 72 interleaved
#define W2r  4608
#define WTOT 13248

// smem word offsets
#define OW0   0                // 4032
#define OW12  4032             // 9216
#define OB    13248            // 2 x 192 (bias double buffer)
#define OZ1   13632            // 64 x 72
#define OZ2   18240
#define OHI   22848            // H interleaved: 64 x 72
#define OQ0   27456            // 64
#define OLD   27520            // 4 x 64
#define OSS   27776            // 4 x 64
#define SMEM_WORDS 28032
#define SMEM_BYTES (SMEM_WORDS * 4)    // 112128 -> 2 CTAs/SM

__device__ __align__(16) unsigned gW[NC][WTOT];
__device__ __align__(16) float gBB[NC][192];

__device__ __forceinline__ float tanh_fast(float x) {
    float r;
    asm("tanh.approx.f32 %0, %1;" : "=f"(r) : "f"(x));
    return r;
}
__device__ __forceinline__ unsigned pack2(float hi_elem, float lo_elem) {
    unsigned r;
    asm("cvt.rn.bf16x2.f32 %0, %1, %2;" : "=r"(r) : "f"(hi_elem), "f"(lo_elem));
    return r;
}
// split (x = even-k, y = odd-k) into packed hi word + packed lo word
__device__ __forceinline__ void split2(float x, float y, unsigned& h, unsigned& l) {
    h = pack2(y, x);
    float hx = __uint_as_float(h << 16);
    float hy = __uint_as_float(h & 0xFFFF0000u);
    l = pack2(y - hy, x - hx);
}
__device__ __forceinline__ void mma16(float (&d)[4], const unsigned* a,
                                      unsigned b0, unsigned b1) {
    asm volatile(
        "mma.sync.aligned.m16n8k16.row.col.f32.bf16.bf16.f32 "
        "{%0,%1,%2,%3}, {%4,%5,%6,%7}, {%8,%9}, {%0,%1,%2,%3};"
        : "+f"(d[0]), "+f"(d[1]), "+f"(d[2]), "+f"(d[3])
        : "r"(a[0]), "r"(a[1]), "r"(a[2]), "r"(a[3]), "r"(b0), "r"(b1));
}
__device__ __forceinline__ void cp16(void* sdst, const void* gsrc) {
    unsigned s = (unsigned)__cvta_generic_to_shared(sdst);
    asm volatile("cp.async.cg.shared.global [%0], [%1], 16;" :: "r"(s), "l"(gsrc));
}
#define CP_COMMIT() asm volatile("cp.async.commit_group;" ::: "memory")
#define CP_WAIT0()  asm volatile("cp.async.wait_group 0;" ::: "memory")
#define CP_WAIT1()  asm volatile("cp.async.wait_group 1;" ::: "memory")

// ---------------- pre-split kernel (interleaved h/l output) ----------------
__global__ void presplit_kernel(const float* __restrict__ W_in,  const float* __restrict__ b_in,
                                const float* __restrict__ W_mu,  const float* __restrict__ b_mu,
                                const float* __restrict__ W_sig, const float* __restrict__ b_sig)
{
    const int cc = blockIdx.x;
    const int tid = threadIdx.x;
    for (int idx = tid; idx < 56 * KPI; idx += blockDim.x) {
        int n = idx / KPI, kp = idx - n * KPI;
        int k0 = 2 * kp, k1 = k0 + 1;
        float v0 = (n < HS && k0 < ZH) ? W_in[cc * HS * ZH + n * ZH + k0] : 0.0f;
        float v1 = (n < HS && k1 < ZH) ? W_in[cc * HS * ZH + n * ZH + k1] : 0.0f;
        unsigned h, l;
        split2(v0, v1, h, l);
        gW[cc][n * KP2 + 2 * kp]     = h;
        gW[cc][n * KP2 + 2 * kp + 1] = l;
    }
    for (int idx = tid; idx < 64 * KPI; idx += blockDim.x) {
        int n = idx / KPI, kp = idx - n * KPI;
        int k0 = 2 * kp, k1 = k0 + 1;
        float m0 = (k0 < HS) ? W_mu [cc * ZH * HS + n * HS + k0] : 0.0f;
        float m1 = (k1 < HS) ? W_mu [cc * ZH * HS + n * HS + k1] : 0.0f;
        float s0 = (k0 < HS) ? W_sig[cc * ZH * HS + n * HS + k0] : 0.0f;
        float s1 = (k1 < HS) ? W_sig[cc * ZH * HS + n * HS + k1] : 0.0f;
        unsigned h, l;
        split2(m0, m1, h, l);
        gW[cc][GW12 + W1r + n * KP2 + 2 * kp]     = h;
        gW[cc][GW12 + W1r + n * KP2 + 2 * kp + 1] = l;
        split2(s0, s1, h, l);
        gW[cc][GW12 + W2r + n * KP2 + 2 * kp]     = h;
        gW[cc][GW12 + W2r + n * KP2 + 2 * kp + 1] = l;
    }
    if (tid < 64) {
        gBB[cc][tid]       = (tid < HS) ? b_in[cc * HS + tid] : 0.0f;
        gBB[cc][64 + tid]  = b_mu [cc * ZH + tid];
        gBB[cc][128 + tid] = b_sig[cc * ZH + tid];
    }
}

// ---------------- main kernel ----------------
__global__ void __launch_bounds__(TPB, 2)
flow_kernel(const float* __restrict__ mean,  const float* __restrict__ logvar,
            const float* __restrict__ eps,
            float* __restrict__ out, int Brows)
{
    extern __shared__ float sm[];
    unsigned* uW0  = (unsigned*)(sm + OW0);
    unsigned* uW12 = (unsigned*)(sm + OW12);
    float*    sZ1  = sm + OZ1;
    float*    sZ2  = sm + OZ2;
    unsigned* uH   = (unsigned*)(sm + OHI);
    float*    sQ0  = sm + OQ0;
    float*    sLD  = sm + OLD;
    float*    sSS  = sm + OSS;

    const int tid  = threadIdx.x;
    const int lane = tid & 31;
    const int wid  = tid >> 5;
    const int wm   = wid & 1;          // m-group: rows 32*wm..+31
    const int wn   = wid >> 1;         // n-quarter (0..3)
    const int gid  = lane >> 2;
    const int tig  = lane & 3;
    const int rb   = 32 * wm;
    const int rowBase = blockIdx.x * MR;

    // ---- prefetch coupling 0: group A = {W0,b}, group B = {W12} ----
    {
        const float4* s0 = (const float4*)(&gW[0][0]);
        float4* d0 = (float4*)(sm + OW0);
        for (int i = tid; i < 4032 / 4; i += TPB) cp16(d0 + i, s0 + i);
        if (tid < 48) cp16((float4*)(sm + OB) + tid, (const float4*)(&gBB[0][0]) + tid);
        CP_COMMIT();
        const float4* s1 = (const float4*)(&gW[0][GW12]);
        float4* d1 = (float4*)(sm + OW12);
        for (int i = tid; i < 9216 / 4; i += TPB) cp16(d1 + i, s1 + i);
        CP_COMMIT();
    }

    // ---- zero H k-pad (kp 28..31, 64 rows), 64-bit stores ----
    if (tid < 256) {
        int r = tid >> 2, kp = 28 + (tid & 3);
        *(uint2*)&uH[r * KP2 + 2 * kp] = make_uint2(0u, 0u);
    }

    // ================= reparam (4 threads/row) =================
    {
        const int rrow = tid >> 2, p = tid & 3;
        float part = 0.0f;
#pragma unroll
        for (int j = 0; j < 8; j++) {
            int q = p + 4 * j;
            size_t g = (size_t)(rowBase + rrow) * 32 + q;
            float4 mv = ((const float4*)mean  )[g];
            float4 lv = ((const float4*)logvar)[g];
            float4 ev = ((const float4*)eps   )[g];
            float4 z4;
            z4.x = fmaf(ev.x, __expf(0.5f * lv.x), mv.x);
            z4.y = fmaf(ev.y, __expf(0.5f * lv.y), mv.y);
            z4.z = fmaf(ev.z, __expf(0.5f * lv.z), mv.z);
            z4.w = fmaf(ev.w, __expf(0.5f * lv.w), mv.w);
            part += lv.x + lv.y + lv.z + lv.w;
            part = fmaf(ev.x, ev.x, part);
            part = fmaf(ev.y, ev.y, part);
            part = fmaf(ev.z, ev.z, part);
            part = fmaf(ev.w, ev.w, part);
            if (q < 16)
                *(float4*)&sZ1[rrow * PZ + 4 * q] = z4;
            else
                *(float4*)&sZ2[rrow * PZ + 4 * (q - 16)] = z4;
        }
        part += __shfl_xor_sync(0xffffffffu, part, 1);
        part += __shfl_xor_sync(0xffffffffu, part, 2);
        if (p == 0) sQ0[rrow] = -0.5f * part;
    }

    float ldp[4] = {0.f, 0.f, 0.f, 0.f};
    float ssp[4] = {0.f, 0.f, 0.f, 0.f};

    // ================= couplings =================
#pragma unroll 1
    for (int cc = 0; cc < NC; cc++) {
        // wait group A of cc ({W0,b}); group B ({W12}) may still stream
        CP_WAIT1();
        __syncthreads();

        const float* sB0 = sm + OB + 192 * (cc & 1);
        const float* sB1 = sB0 + 64;
        const float* sB2 = sB0 + 128;
        const float* sZa = (cc & 1) ? sZ2 : sZ1;
        float*       sZu = (cc & 1) ? sZ1 : sZ2;

        // ---- GEMM1: H = tanh(Za @ W0^T + b0); m32 x n16 (wn3: n8) ----
        {
            const int NT = (wn < 3) ? 2 : 1;   // 7 n-tiles over 4 quarters
            float acc[2][2][4] = {};
#pragma unroll
            for (int c = 0; c < 4; c++) {
                unsigned ah[2][4], al[2][4];
#pragma unroll
                for (int s2 = 0; s2 < 2; s2++) {
                    int ra0 = rb + 16 * s2 + gid, ra1 = ra0 + 8;
                    float2 v00 = ((const float2*)&sZa[ra0 * PZ])[tig +     8 * c];
                    float2 v10 = ((const float2*)&sZa[ra1 * PZ])[tig +     8 * c];
                    float2 v01 = ((const float2*)&sZa[ra0 * PZ])[tig + 4 + 8 * c];
                    float2 v11 = ((const float2*)&sZa[ra1 * PZ])[tig + 4 + 8 * c];
                    split2(v00.x, v00.y, ah[s2][0], al[s2][0]);
                    split2(v10.x, v10.y, ah[s2][1], al[s2][1]);
                    split2(v01.x, v01.y, ah[s2][2], al[s2][2]);
                    split2(v11.x, v11.y, ah[s2][3], al[s2][3]);
                }
#pragma unroll
                for (int nn = 0; nn < 2; nn++) {
                    if (nn >= NT) break;
                    int nrow = 8 * (2 * wn + nn) + gid;
                    uint2 b0 = *(const uint2*)&uW0[nrow * KP2 + 2 * (tig +     8 * c)];
                    uint2 b1 = *(const uint2*)&uW0[nrow * KP2 + 2 * (tig + 4 + 8 * c)];
#pragma unroll
                    for (int s2 = 0; s2 < 2; s2++) {
                        mma16(acc[s2][nn], ah[s2], b0.x, b1.x);
                        mma16(acc[s2][nn], ah[s2], b0.y, b1.y);
                        mma16(acc[s2][nn], al[s2], b0.x, b1.x);
                    }
                }
            }
            // epilogue: bias + tanh, write H pre-split/packed (64-bit stores)
#pragma unroll
            for (int nn = 0; nn < 2; nn++) {
                if (nn >= NT) break;
                int nt  = 2 * wn + nn;
                int col = 8 * nt + 2 * tig;
                int kp  = 4 * nt + tig;
                float bb0 = sB0[col], bb1 = sB0[col + 1];
#pragma unroll
                for (int s2 = 0; s2 < 2; s2++) {
                    int ra0 = rb + 16 * s2 + gid, ra1 = ra0 + 8;
                    float t00 = tanh_fast(acc[s2][nn][0] + bb0);
                    float t01 = tanh_fast(acc[s2][nn][1] + bb1);
                    float t10 = tanh_fast(acc[s2][nn][2] + bb0);
                    float t11 = tanh_fast(acc[s2][nn][3] + bb1);
                    unsigned h, l;
                    split2(t00, t01, h, l);
                    *(uint2*)&uH[ra0 * KP2 + 2 * kp] = make_uint2(h, l);
                    split2(t10, t11, h, l);
                    *(uint2*)&uH[ra1 * KP2 + 2 * kp] = make_uint2(h, l);
                }
            }
        }
        CP_WAIT0();                    // W12(cc) landed
        __syncthreads();               // H visible; W0(cc) reads done

        // ---- prefetch {W0,b}(cc+1) (overlaps GEMM2; W0 buffer now free) ----
        if (cc < 3) {
            const float4* s0 = (const float4*)(&gW[cc + 1][0]);
            float4* d0 = (float4*)(sm + OW0);
            for (int i = tid; i < 4032 / 4; i += TPB) cp16(d0 + i, s0 + i);
            if (tid < 48)
                cp16((float4*)(sm + OB + 192 * ((cc + 1) & 1)) + tid,
                     (const float4*)(&gBB[cc + 1][0]) + tid);
            CP_COMMIT();
        }

        // ---- GEMM2: mu/sig heads; m32 x n16 (2 tiles), K=64 ----
        {
            float am [2][2][4] = {};
            float as2[2][2][4] = {};
#pragma unroll
            for (int c = 0; c < 4; c++) {
                unsigned ah[2][4], al[2][4];
#pragma unroll
                for (int s2 = 0; s2 < 2; s2++) {
                    int ra0 = rb + 16 * s2 + gid, ra1 = ra0 + 8;
                    uint2 a0 = *(const uint2*)&uH[ra0 * KP2 + 2 * (tig +     8 * c)];
                    uint2 a1 = *(const uint2*)&uH[ra1 * KP2 + 2 * (tig +     8 * c)];
                    uint2 a2 = *(const uint2*)&uH[ra0 * KP2 + 2 * (tig + 4 + 8 * c)];
                    uint2 a3 = *(const uint2*)&uH[ra1 * KP2 + 2 * (tig + 4 + 8 * c)];
                    ah[s2][0] = a0.x; al[s2][0] = a0.y;
                    ah[s2][1] = a1.x; al[s2][1] = a1.y;
                    ah[s2][2] = a2.x; al[s2][2] = a2.y;
                    ah[s2][3] = a3.x; al[s2][3] = a3.y;
                }
#pragma unroll
                for (int nn = 0; nn < 2; nn++) {
                    int nrow = 8 * (2 * wn + nn) + gid;
                    uint2 b0 = *(const uint2*)&uW12[W1r + nrow * KP2 + 2 * (tig +     8 * c)];
                    uint2 b1 = *(const uint2*)&uW12[W1r + nrow * KP2 + 2 * (tig + 4 + 8 * c)];
#pragma unroll
                    for (int s2 = 0; s2 < 2; s2++) {
                        mma16(am[s2][nn], ah[s2], b0.x, b1.x);
                        mma16(am[s2][nn], ah[s2], b0.y, b1.y);
                        mma16(am[s2][nn], al[s2], b0.x, b1.x);
                    }
                    b0 = *(const uint2*)&uW12[W2r + nrow * KP2 + 2 * (tig +     8 * c)];
                    b1 = *(const uint2*)&uW12[W2r + nrow * KP2 + 2 * (tig + 4 + 8 * c)];
#pragma unroll
                    for (int s2 = 0; s2 < 2; s2++) {
                        mma16(as2[s2][nn], ah[s2], b0.x, b1.x);
                        mma16(as2[s2][nn], ah[s2], b0.y, b1.y);
                        mma16(as2[s2][nn], al[s2], b0.x, b1.x);
                    }
                }
            }
            // ---- epilogue: sig, z update, logdet ----
            const bool fin = (cc >= 2);
#pragma unroll
            for (int s2 = 0; s2 < 2; s2++) {
                int ra0 = rb + 16 * s2 + gid, ra1 = ra0 + 8;
#pragma unroll
                for (int nn = 0; nn < 2; nn++) {
                    int col = 8 * (2 * wn + nn) + 2 * tig;
#pragma unroll
                    for (int d = 0; d < 2; d++) {
                        float bm = sB1[col + d];
                        float bs = sB2[col + d];
                        {
                            float mu = am[s2][nn][d] + bm;
                            float x  = as2[s2][nn][d] + bs;
                            float sg = fmaf(tanh_fast(0.5f * x), 0.5f, 0.5f);
                            ldp[2 * s2] += __logf(sg);
                            float zn = fmaf(sZu[ra0 * PZ + col + d], sg, mu);
                            sZu[ra0 * PZ + col + d] = zn;
                            if (fin) ssp[2 * s2] = fmaf(zn, zn, ssp[2 * s2]);
                        }
                        {
                            float mu = am[s2][nn][d + 2] + bm;
                            float x  = as2[s2][nn][d + 2] + bs;
                            float sg = fmaf(tanh_fast(0.5f * x), 0.5f, 0.5f);
                            ldp[2 * s2 + 1] += __logf(sg);
                            float zn = fmaf(sZu[ra1 * PZ + col + d], sg, mu);
                            sZu[ra1 * PZ + col + d] = zn;
                            if (fin) ssp[2 * s2 + 1] = fmaf(zn, zn, ssp[2 * s2 + 1]);
                        }
                    }
                }
            }
        }
        __syncthreads();               // z updated; W12(cc) reads done

        // ---- prefetch {W12}(cc+1) (overlaps next GEMM1) ----
        if (cc < 3) {
            const float4* s1 = (const float4*)(&gW[cc + 1][GW12]);
            float4* d1 = (float4*)(sm + OW12);
            for (int i = tid; i < 9216 / 4; i += TPB) cp16(d1 + i, s1 + i);
            CP_COMMIT();
        }
    }

    // ================= write z (coalesced float4) =================
#pragma unroll
    for (int i = 0; i < 8; i++) {
        int idx = tid + TPB * i;            // 0..2047
        int row = idx >> 5, q = idx & 31;
        float4 v = (q < 16)
            ? *(const float4*)&sZ1[row * PZ + 4 * q]
            : *(const float4*)&sZ2[row * PZ + 4 * (q - 16)];
        ((float4*)out)[(size_t)(rowBase + row) * 32 + q] = v;
    }

    // ================= densities =================
#pragma unroll
    for (int s = 0; s < 4; s++) {
        float l = ldp[s], v = ssp[s];
        l += __shfl_xor_sync(0xffffffffu, l, 1);
        l += __shfl_xor_sync(0xffffffffu, l, 2);
        v += __shfl_xor_sync(0xffffffffu, v, 1);
        v += __shfl_xor_sync(0xffffffffu, v, 2);
        if (tig == 0) {
            int row = rb + 16 * (s >> 1) + 8 * (s & 1) + gid;
            sLD[wn * 64 + row] = l;
            sSS[wn * 64 + row] = v;
        }
    }
    __syncthreads();
    if (tid < 64) {
        float l = sLD[tid] + sLD[64 + tid] + sLD[128 + tid] + sLD[192 + tid];
        float s = sSS[tid] + sSS[64 + tid] + sSS[128 + tid] + sSS[192 + tid];
        size_t base = (size_t)Brows * ZZ;
        out[base + rowBase + tid]         = -0.5f * s;
        out[base + Brows + rowBase + tid] = sQ0[tid] - l;
    }
}

extern "C" void kernel_launch(void* const* d_in, const int* in_sizes, int n_in,
                              void* d_out, int out_size)
{
    const float* mean   = (const float*)d_in[0];
    const float* logvar = (const float*)d_in[1];
    const float* eps    = (const float*)d_in[2];
    const float* W_in   = (const float*)d_in[3];
    const float* b_in   = (const float*)d_in[4];
    const float* W_mu   = (const float*)d_in[5];
    const float* b_mu   = (const float*)d_in[6];
    const float* W_sig  = (const float*)d_in[7];
    const float* b_sig  = (const float*)d_in[8];
    float* out = (float*)d_out;

    int Brows = in_sizes[0] / ZZ;

    cudaFuncSetAttribute(flow_kernel, cudaFuncAttributeMaxDynamicSharedMemorySize, SMEM_BYTES);

    presplit_kernel<<<NC, 256>>>(W_in, b_in, W_mu, b_mu, W_sig, b_sig);
    flow_kernel<<<Brows / MR, TPB, SMEM_BYTES>>>(mean, logvar, eps, out, Brows);
}

// round 15
// speedup vs baseline: 1.1382x; 1.1382x over previous
#include <cuda_runtime.h>
#include <cstdint>

// Flow1 via mma.sync m16n8k16 bf16 (3-product compensation), packed pre-split
// weights, m32 x n16 warp tiles at 2 CTAs/SM, group-counted cp.async staging.
// R15 = R13 layout (separate hi/lo arrays, PZ=72) + product-major MMA issue
// order: asm volatile fixes program order, so R13's 3 back-to-back products
// into one accumulator serialized on HMMA RAW latency. Now all accumulators'
// hh products issue first, then hl, then lh (reuse distance 4-8).
// B=262144 rows, Z=128, ZH=64, HS=50 (padded 56), 4 couplings.
// Out: [ z (B*128) | logpz (B) | logqz (B) ] fp32.

#define ZZ 128
#define ZH 64
#define HS 50
#define NC 4
#define TPB 256
#define MR 64
#define PZ 72      // fp32 z pitch (floats); 72 % 32 = 8 -> conflict-free LDS.64
#define KPI 36     // k-pair pitch (words)

// global packed-weight layout (per coupling), words
#define W0H 0                  // 56 n x 36 kp
#define W0L 2016
#define GW12 4032              // W1/W2 block
#define W1Hr 0
#define W1Lr 2304
#define W2Hr 4608
#define W2Lr 6912
#define WTOT 13248

// smem word offsets
#define OW0   0                // 4032
#define OW12  4032             // 9216
#define OB    13248            // 2 x 192 (bias double buffer)
#define OZ1   13632            // 64 x 72
#define OZ2   18240
#define OHH   22848            // 64 x 36
#define OHL   25152
#define OQ0   27456            // 64
#define OLD   27520            // 4 x 64
#define OSS   27776            // 4 x 64
#define SMEM_WORDS 28032
#define SMEM_BYTES (SMEM_WORDS * 4)    // 112128 -> 2 CTAs/SM

__device__ __align__(16) unsigned gW[NC][WTOT];
__device__ __align__(16) float gBB[NC][192];

__device__ __forceinline__ float tanh_fast(float x) {
    float r;
    asm("tanh.approx.f32 %0, %1;" : "=f"(r) : "f"(x));
    return r;
}
__device__ __forceinline__ unsigned pack2(float hi_elem, float lo_elem) {
    unsigned r;
    asm("cvt.rn.bf16x2.f32 %0, %1, %2;" : "=r"(r) : "f"(hi_elem), "f"(lo_elem));
    return r;
}
// split (x = even-k, y = odd-k) into packed hi word + packed lo word
__device__ __forceinline__ void split2(float x, float y, unsigned& h, unsigned& l) {
    h = pack2(y, x);
    float hx = __uint_as_float(h << 16);
    float hy = __uint_as_float(h & 0xFFFF0000u);
    l = pack2(y - hy, x - hx);
}
__device__ __forceinline__ void mma16(float (&d)[4], const unsigned* a,
                                      unsigned b0, unsigned b1) {
    asm volatile(
        "mma.sync.aligned.m16n8k16.row.col.f32.bf16.bf16.f32 "
        "{%0,%1,%2,%3}, {%4,%5,%6,%7}, {%8,%9}, {%0,%1,%2,%3};"
        : "+f"(d[0]), "+f"(d[1]), "+f"(d[2]), "+f"(d[3])
        : "r"(a[0]), "r"(a[1]), "r"(a[2]), "r"(a[3]), "r"(b0), "r"(b1));
}
__device__ __forceinline__ void cp16(void* sdst, const void* gsrc) {
    unsigned s = (unsigned)__cvta_generic_to_shared(sdst);
    asm volatile("cp.async.cg.shared.global [%0], [%1], 16;" :: "r"(s), "l"(gsrc));
}
#define CP_COMMIT() asm volatile("cp.async.commit_group;" ::: "memory")
#define CP_WAIT0()  asm volatile("cp.async.wait_group 0;" ::: "memory")
#define CP_WAIT1()  asm volatile("cp.async.wait_group 1;" ::: "memory")

// ---------------- pre-split kernel ----------------
__global__ void presplit_kernel(const float* __restrict__ W_in,  const float* __restrict__ b_in,
                                const float* __restrict__ W_mu,  const float* __restrict__ b_mu,
                                const float* __restrict__ W_sig, const float* __restrict__ b_sig)
{
    const int cc = blockIdx.x;
    const int tid = threadIdx.x;
    for (int idx = tid; idx < 56 * KPI; idx += blockDim.x) {
        int n = idx / KPI, kp = idx - n * KPI;
        int k0 = 2 * kp, k1 = k0 + 1;
        float v0 = (n < HS && k0 < ZH) ? W_in[cc * HS * ZH + n * ZH + k0] : 0.0f;
        float v1 = (n < HS && k1 < ZH) ? W_in[cc * HS * ZH + n * ZH + k1] : 0.0f;
        unsigned h, l;
        split2(v0, v1, h, l);
        gW[cc][W0H + idx] = h;
        gW[cc][W0L + idx] = l;
    }
    for (int idx = tid; idx < 64 * KPI; idx += blockDim.x) {
        int n = idx / KPI, kp = idx - n * KPI;
        int k0 = 2 * kp, k1 = k0 + 1;
        float m0 = (k0 < HS) ? W_mu [cc * ZH * HS + n * HS + k0] : 0.0f;
        float m1 = (k1 < HS) ? W_mu [cc * ZH * HS + n * HS + k1] : 0.0f;
        float s0 = (k0 < HS) ? W_sig[cc * ZH * HS + n * HS + k0] : 0.0f;
        float s1 = (k1 < HS) ? W_sig[cc * ZH * HS + n * HS + k1] : 0.0f;
        unsigned h, l;
        split2(m0, m1, h, l);
        gW[cc][GW12 + W1Hr + idx] = h;
        gW[cc][GW12 + W1Lr + idx] = l;
        split2(s0, s1, h, l);
        gW[cc][GW12 + W2Hr + idx] = h;
        gW[cc][GW12 + W2Lr + idx] = l;
    }
    if (tid < 64) {
        gBB[cc][tid]       = (tid < HS) ? b_in[cc * HS + tid] : 0.0f;
        gBB[cc][64 + tid]  = b_mu [cc * ZH + tid];
        gBB[cc][128 + tid] = b_sig[cc * ZH + tid];
    }
}

// ---------------- main kernel ----------------
__global__ void __launch_bounds__(TPB, 2)
flow_kernel(const float* __restrict__ mean,  const float* __restrict__ logvar,
            const float* __restrict__ eps,
            float* __restrict__ out, int Brows)
{
    extern __shared__ float sm[];
    unsigned* uW0  = (unsigned*)(sm + OW0);
    unsigned* uW12 = (unsigned*)(sm + OW12);
    float*    sZ1  = sm + OZ1;
    float*    sZ2  = sm + OZ2;
    unsigned* uHH  = (unsigned*)(sm + OHH);
    unsigned* uHL  = (unsigned*)(sm + OHL);
    float*    sQ0  = sm + OQ0;
    float*    sLD  = sm + OLD;
    float*    sSS  = sm + OSS;

    const int tid  = threadIdx.x;
    const int lane = tid & 31;
    const int wid  = tid >> 5;
    const int wm   = wid & 1;          // m-group: rows 32*wm..+31
    const int wn   = wid >> 1;         // n-quarter (0..3)
    const int gid  = lane >> 2;
    const int tig  = lane & 3;
    const int rb   = 32 * wm;
    const int rowBase = blockIdx.x * MR;

    // ---- prefetch coupling 0: group A = {W0,b}, group B = {W12} ----
    {
        const float4* s0 = (const float4*)(&gW[0][0]);
        float4* d0 = (float4*)(sm + OW0);
        for (int i = tid; i < 4032 / 4; i += TPB) cp16(d0 + i, s0 + i);
        if (tid < 48) cp16((float4*)(sm + OB) + tid, (const float4*)(&gBB[0][0]) + tid);
        CP_COMMIT();
        const float4* s1 = (const float4*)(&gW[0][GW12]);
        float4* d1 = (float4*)(sm + OW12);
        for (int i = tid; i < 9216 / 4; i += TPB) cp16(d1 + i, s1 + i);
        CP_COMMIT();
    }

    // ---- zero H k-pad (kp 28..31, 64 rows) ----
    if (tid < 256) {
        int r = tid >> 2, kp = 28 + (tid & 3);
        uHH[r * KPI + kp] = 0u;
        uHL[r * KPI + kp] = 0u;
    }

    // ================= reparam (4 threads/row) =================
    {
        const int rrow = tid >> 2, p = tid & 3;
        float part = 0.0f;
#pragma unroll
        for (int j = 0; j < 8; j++) {
            int q = p + 4 * j;
            size_t g = (size_t)(rowBase + rrow) * 32 + q;
            float4 mv = ((const float4*)mean  )[g];
            float4 lv = ((const float4*)logvar)[g];
            float4 ev = ((const float4*)eps   )[g];
            float4 z4;
            z4.x = fmaf(ev.x, __expf(0.5f * lv.x), mv.x);
            z4.y = fmaf(ev.y, __expf(0.5f * lv.y), mv.y);
            z4.z = fmaf(ev.z, __expf(0.5f * lv.z), mv.z);
            z4.w = fmaf(ev.w, __expf(0.5f * lv.w), mv.w);
            part += lv.x + lv.y + lv.z + lv.w;
            part = fmaf(ev.x, ev.x, part);
            part = fmaf(ev.y, ev.y, part);
            part = fmaf(ev.z, ev.z, part);
            part = fmaf(ev.w, ev.w, part);
            if (q < 16)
                *(float4*)&sZ1[rrow * PZ + 4 * q] = z4;
            else
                *(float4*)&sZ2[rrow * PZ + 4 * (q - 16)] = z4;
        }
        part += __shfl_xor_sync(0xffffffffu, part, 1);
        part += __shfl_xor_sync(0xffffffffu, part, 2);
        if (p == 0) sQ0[rrow] = -0.5f * part;
    }

    float ldp[4] = {0.f, 0.f, 0.f, 0.f};
    float ssp[4] = {0.f, 0.f, 0.f, 0.f};

    // ================= couplings =================
#pragma unroll 1
    for (int cc = 0; cc < NC; cc++) {
        // wait group A of cc ({W0,b}); group B ({W12}) may still stream
        CP_WAIT1();
        __syncthreads();

        const float* sB0 = sm + OB + 192 * (cc & 1);
        const float* sB1 = sB0 + 64;
        const float* sB2 = sB0 + 128;
        const float* sZa = (cc & 1) ? sZ2 : sZ1;
        float*       sZu = (cc & 1) ? sZ1 : sZ2;

        // ---- GEMM1: H = tanh(Za @ W0^T + b0); m32 x n16 (wn3: n8) ----
        {
            const int NT = (wn < 3) ? 2 : 1;   // 7 n-tiles over 4 quarters
            float acc[2][2][4] = {};
#pragma unroll
            for (int c = 0; c < 4; c++) {
                unsigned ah[2][4], al[2][4];
#pragma unroll
                for (int s2 = 0; s2 < 2; s2++) {
                    int ra0 = rb + 16 * s2 + gid, ra1 = ra0 + 8;
                    float2 v00 = ((const float2*)&sZa[ra0 * PZ])[tig +     8 * c];
                    float2 v10 = ((const float2*)&sZa[ra1 * PZ])[tig +     8 * c];
                    float2 v01 = ((const float2*)&sZa[ra0 * PZ])[tig + 4 + 8 * c];
                    float2 v11 = ((const float2*)&sZa[ra1 * PZ])[tig + 4 + 8 * c];
                    split2(v00.x, v00.y, ah[s2][0], al[s2][0]);
                    split2(v10.x, v10.y, ah[s2][1], al[s2][1]);
                    split2(v01.x, v01.y, ah[s2][2], al[s2][2]);
                    split2(v11.x, v11.y, ah[s2][3], al[s2][3]);
                }
                unsigned bh0[2], bh1[2], bl0[2], bl1[2];
#pragma unroll
                for (int nn = 0; nn < 2; nn++) {
                    if (nn >= NT) break;
                    int nrow = 8 * (2 * wn + nn) + gid;
                    bh0[nn] = uW0[W0H + nrow * KPI + tig +     8 * c];
                    bh1[nn] = uW0[W0H + nrow * KPI + tig + 4 + 8 * c];
                    bl0[nn] = uW0[W0L + nrow * KPI + tig +     8 * c];
                    bl1[nn] = uW0[W0L + nrow * KPI + tig + 4 + 8 * c];
                }
                // product-major issue: hh for all accs, then hl, then lh
#pragma unroll
                for (int nn = 0; nn < 2; nn++) {
                    if (nn >= NT) break;
#pragma unroll
                    for (int s2 = 0; s2 < 2; s2++)
                        mma16(acc[s2][nn], ah[s2], bh0[nn], bh1[nn]);
                }
#pragma unroll
                for (int nn = 0; nn < 2; nn++) {
                    if (nn >= NT) break;
#pragma unroll
                    for (int s2 = 0; s2 < 2; s2++)
                        mma16(acc[s2][nn], ah[s2], bl0[nn], bl1[nn]);
                }
#pragma unroll
                for (int nn = 0; nn < 2; nn++) {
                    if (nn >= NT) break;
#pragma unroll
                    for (int s2 = 0; s2 < 2; s2++)
                        mma16(acc[s2][nn], al[s2], bh0[nn], bh1[nn]);
                }
            }
            // epilogue: bias + tanh, write H pre-split/packed
#pragma unroll
            for (int nn = 0; nn < 2; nn++) {
                if (nn >= NT) break;
                int nt  = 2 * wn + nn;
                int col = 8 * nt + 2 * tig;
                int kp  = 4 * nt + tig;
                float bb0 = sB0[col], bb1 = sB0[col + 1];
#pragma unroll
                for (int s2 = 0; s2 < 2; s2++) {
                    int ra0 = rb + 16 * s2 + gid, ra1 = ra0 + 8;
                    float t00 = tanh_fast(acc[s2][nn][0] + bb0);
                    float t01 = tanh_fast(acc[s2][nn][1] + bb1);
                    float t10 = tanh_fast(acc[s2][nn][2] + bb0);
                    float t11 = tanh_fast(acc[s2][nn][3] + bb1);
                    unsigned h, l;
                    split2(t00, t01, h, l);
                    uHH[ra0 * KPI + kp] = h;
                    uHL[ra0 * KPI + kp] = l;
                    split2(t10, t11, h, l);
                    uHH[ra1 * KPI + kp] = h;
                    uHL[ra1 * KPI + kp] = l;
                }
            }
        }
        CP_WAIT0();                    // W12(cc) landed
        __syncthreads();               // H visible; W0(cc) reads done

        // ---- prefetch {W0,b}(cc+1) (overlaps GEMM2; W0 buffer now free) ----
        if (cc < 3) {
            const float4* s0 = (const float4*)(&gW[cc + 1][0]);
            float4* d0 = (float4*)(sm + OW0);
            for (int i = tid; i < 4032 / 4; i += TPB) cp16(d0 + i, s0 + i);
            if (tid < 48)
                cp16((float4*)(sm + OB + 192 * ((cc + 1) & 1)) + tid,
                     (const float4*)(&gBB[cc + 1][0]) + tid);
            CP_COMMIT();
        }

        // ---- GEMM2: mu/sig heads; m32 x n16 (2 tiles), K=64 ----
        {
            float am [2][2][4] = {};
            float as2[2][2][4] = {};
#pragma unroll
            for (int c = 0; c < 4; c++) {
                unsigned ah[2][4], al[2][4];
#pragma unroll
                for (int s2 = 0; s2 < 2; s2++) {
                    int ra0 = rb + 16 * s2 + gid, ra1 = ra0 + 8;
                    ah[s2][0] = uHH[ra0 * KPI + tig +     8 * c];
                    ah[s2][1] = uHH[ra1 * KPI + tig +     8 * c];
                    ah[s2][2] = uHH[ra0 * KPI + tig + 4 + 8 * c];
                    ah[s2][3] = uHH[ra1 * KPI + tig + 4 + 8 * c];
                    al[s2][0] = uHL[ra0 * KPI + tig +     8 * c];
                    al[s2][1] = uHL[ra1 * KPI + tig +     8 * c];
                    al[s2][2] = uHL[ra0 * KPI + tig + 4 + 8 * c];
                    al[s2][3] = uHL[ra1 * KPI + tig + 4 + 8 * c];
                }
                unsigned b1h0[2], b1h1[2], b1l0[2], b1l1[2];
                unsigned b2h0[2], b2h1[2], b2l0[2], b2l1[2];
#pragma unroll
                for (int nn = 0; nn < 2; nn++) {
                    int nrow = 8 * (2 * wn + nn) + gid;
                    b1h0[nn] = uW12[W1Hr + nrow * KPI + tig +     8 * c];
                    b1h1[nn] = uW12[W1Hr + nrow * KPI + tig + 4 + 8 * c];
                    b1l0[nn] = uW12[W1Lr + nrow * KPI + tig +     8 * c];
                    b1l1[nn] = uW12[W1Lr + nrow * KPI + tig + 4 + 8 * c];
                    b2h0[nn] = uW12[W2Hr + nrow * KPI + tig +     8 * c];
                    b2h1[nn] = uW12[W2Hr + nrow * KPI + tig + 4 + 8 * c];
                    b2l0[nn] = uW12[W2Lr + nrow * KPI + tig +     8 * c];
                    b2l1[nn] = uW12[W2Lr + nrow * KPI + tig + 4 + 8 * c];
                }
                // product-major over all 8 accumulators (reuse distance 8)
#pragma unroll
                for (int nn = 0; nn < 2; nn++)
#pragma unroll
                    for (int s2 = 0; s2 < 2; s2++)
                        mma16(am[s2][nn], ah[s2], b1h0[nn], b1h1[nn]);
#pragma unroll
                for (int nn = 0; nn < 2; nn++)
#pragma unroll
                    for (int s2 = 0; s2 < 2; s2++)
                        mma16(as2[s2][nn], ah[s2], b2h0[nn], b2h1[nn]);
#pragma unroll
                for (int nn = 0; nn < 2; nn++)
#pragma unroll
                    for (int s2 = 0; s2 < 2; s2++)
                        mma16(am[s2][nn], ah[s2], b1l0[nn], b1l1[nn]);
#pragma unroll
                for (int nn = 0; nn < 2; nn++)
#pragma unroll
                    for (int s2 = 0; s2 < 2; s2++)
                        mma16(as2[s2][nn], ah[s2], b2l0[nn], b2l1[nn]);
#pragma unroll
                for (int nn = 0; nn < 2; nn++)
#pragma unroll
                    for (int s2 = 0; s2 < 2; s2++)
                        mma16(am[s2][nn], al[s2], b1h0[nn], b1h1[nn]);
#pragma unroll
                for (int nn = 0; nn < 2; nn++)
#pragma unroll
                    for (int s2 = 0; s2 < 2; s2++)
                        mma16(as2[s2][nn], al[s2], b2h0[nn], b2h1[nn]);
            }
            // ---- epilogue: sig, z update, logdet ----
            const bool fin = (cc >= 2);
#pragma unroll
            for (int s2 = 0; s2 < 2; s2++) {
                int ra0 = rb + 16 * s2 + gid, ra1 = ra0 + 8;
#pragma unroll
                for (int nn = 0; nn < 2; nn++) {
                    int col = 8 * (2 * wn + nn) + 2 * tig;
#pragma unroll
                    for (int d = 0; d < 2; d++) {
                        float bm = sB1[col + d];
                        float bs = sB2[col + d];
                        {
                            float mu = am[s2][nn][d] + bm;
                            float x  = as2[s2][nn][d] + bs;
                            float sg = fmaf(tanh_fast(0.5f * x), 0.5f, 0.5f);
                            ldp[2 * s2] += __logf(sg);
                            float zn = fmaf(sZu[ra0 * PZ + col + d], sg, mu);
                            sZu[ra0 * PZ + col + d] = zn;
                            if (fin) ssp[2 * s2] = fmaf(zn, zn, ssp[2 * s2]);
                        }
                        {
                            float mu = am[s2][nn][d + 2] + bm;
                            float x  = as2[s2][nn][d + 2] + bs;
                            float sg = fmaf(tanh_fast(0.5f * x), 0.5f, 0.5f);
                            ldp[2 * s2 + 1] += __logf(sg);
                            float zn = fmaf(sZu[ra1 * PZ + col + d], sg, mu);
                            sZu[ra1 * PZ + col + d] = zn;
                            if (fin) ssp[2 * s2 + 1] = fmaf(zn, zn, ssp[2 * s2 + 1]);
                        }
                    }
                }
            }
        }
        __syncthreads();               // z updated; W12(cc) reads done

        // ---- prefetch {W12}(cc+1) (overlaps next GEMM1) ----
        if (cc < 3) {
            const float4* s1 = (const float4*)(&gW[cc + 1][GW12]);
            float4* d1 = (float4*)(sm + OW12);
            for (int i = tid; i < 9216 / 4; i += TPB) cp16(d1 + i, s1 + i);
            CP_COMMIT();
        }
    }

    // ================= write z (coalesced float4) =================
#pragma unroll
    for (int i = 0; i < 8; i++) {
        int idx = tid + TPB * i;            // 0..2047
        int row = idx >> 5, q = idx & 31;
        float4 v = (q < 16)
            ? *(const float4*)&sZ1[row * PZ + 4 * q]
            : *(const float4*)&sZ2[row * PZ + 4 * (q - 16)];
        ((float4*)out)[(size_t)(rowBase + row) * 32 + q] = v;
    }

    // ================= densities =================
#pragma unroll
    for (int s = 0; s < 4; s++) {
        float l = ldp[s], v = ssp[s];
        l += __shfl_xor_sync(0xffffffffu, l, 1);
        l += __shfl_xor_sync(0xffffffffu, l, 2);
        v += __shfl_xor_sync(0xffffffffu, v, 1);
        v += __shfl_xor_sync(0xffffffffu, v, 2);
        if (tig == 0) {
            int row = rb + 16 * (s >> 1) + 8 * (s & 1) + gid;
            sLD[wn * 64 + row] = l;
            sSS[wn * 64 + row] = v;
        }
    }
    __syncthreads();
    if (tid < 64) {
        float l = sLD[tid] + sLD[64 + tid] + sLD[128 + tid] + sLD[192 + tid];
        float s = sSS[tid] + sSS[64 + tid] + sSS[128 + tid] + sSS[192 + tid];
        size_t base = (size_t)Brows * ZZ;
        out[base + rowBase + tid]         = -0.5f * s;
        out[base + Brows + rowBase + tid] = sQ0[tid] - l;
    }
}

extern "C" void kernel_launch(void* const* d_in, const int* in_sizes, int n_in,
                              void* d_out, int out_size)
{
    const float* mean   = (const float*)d_in[0];
    const float* logvar = (const float*)d_in[1];
    const float* eps    = (const float*)d_in[2];
    const float* W_in   = (const float*)d_in[3];
    const float* b_in   = (const float*)d_in[4];
    const float* W_mu   = (const float*)d_in[5];
    const float* b_mu   = (const float*)d_in[6];
    const float* W_sig  = (const float*)d_in[7];
    const float* b_sig  = (const float*)d_in[8];
    float* out = (float*)d_out;

    int Brows = in_sizes[0] / ZZ;

    cudaFuncSetAttribute(flow_kernel, cudaFuncAttributeMaxDynamicSharedMemorySize, SMEM_BYTES);

    presplit_kernel<<<NC, 256>>>(W_in, b_in, W_mu, b_mu, W_sig, b_sig);
    flow_kernel<<<Brows / MR, TPB, SMEM_BYTES>>>(mean, logvar, eps, out, Brows);
}